// round 10
// baseline (speedup 1.0000x reference)
#include <cuda_runtime.h>
#include <cuda_fp16.h>
#include <cstdint>

#define BATCH 2
#define SEQ 2048
#define HID 1024
#define NHEADS 16
#define HDIM 64

// fp16 scratch (device globals: allocation-free).
__device__ __align__(16) __half g_xh[BATCH * SEQ * HID];
__device__ __align__(16) __half g_wh[3 * HID * HID];
__device__ __align__(16) __half g_q[BATCH * NHEADS * SEQ * HDIM];
__device__ __align__(16) __half g_k[BATCH * NHEADS * SEQ * HDIM];
__device__ __align__(16) __half g_v[BATCH * NHEADS * SEQ * HDIM];

__device__ __forceinline__ uint32_t h2u(__half2 h) {
    return *reinterpret_cast<uint32_t*>(&h);
}

__device__ __forceinline__ void ldsm_x4(uint32_t addr, uint32_t r[4]) {
    asm volatile("ldmatrix.sync.aligned.m8n8.x4.shared.b16 {%0,%1,%2,%3}, [%4];"
        : "=r"(r[0]), "=r"(r[1]), "=r"(r[2]), "=r"(r[3]) : "r"(addr));
}
__device__ __forceinline__ void ldsm_x4_t(uint32_t addr, uint32_t r[4]) {
    asm volatile("ldmatrix.sync.aligned.m8n8.x4.trans.shared.b16 {%0,%1,%2,%3}, [%4];"
        : "=r"(r[0]), "=r"(r[1]), "=r"(r[2]), "=r"(r[3]) : "r"(addr));
}

__device__ __forceinline__ void mma16(float c[4], const uint32_t a[4], const uint32_t b[2]) {
    asm volatile(
        "mma.sync.aligned.m16n8k16.row.col.f32.f16.f16.f32 "
        "{%0,%1,%2,%3}, {%4,%5,%6,%7}, {%8,%9}, {%0,%1,%2,%3};\n"
        : "+f"(c[0]), "+f"(c[1]), "+f"(c[2]), "+f"(c[3])
        : "r"(a[0]), "r"(a[1]), "r"(a[2]), "r"(a[3]), "r"(b[0]), "r"(b[1]));
}

__device__ __forceinline__ void cp_async16(void* smem_dst, const void* gmem_src) {
    uint32_t s = (uint32_t)__cvta_generic_to_shared(smem_dst);
    asm volatile("cp.async.ca.shared.global [%0], [%1], 16;" :: "r"(s), "l"(gmem_src));
}
#define CP_COMMIT() asm volatile("cp.async.commit_group;" ::: "memory")
#define CP_WAIT(n)  asm volatile("cp.async.wait_group %0;" :: "n"(n) : "memory")

#define LOG2E 1.44269504f

// ============================================================================
// Convert fp32 -> fp16 (X and three W). 16 elems/thread.
// ============================================================================
__global__ void __launch_bounds__(256) convert_kernel(
    const float* __restrict__ X,
    const float* __restrict__ Wq, const float* __restrict__ Wk,
    const float* __restrict__ Wv)
{
    const int z = blockIdx.y;
    const float* src = (z == 0) ? X : (z == 1) ? Wq : (z == 2) ? Wk : Wv;
    __half* dst = (z == 0) ? g_xh : g_wh + (size_t)(z - 1) * HID * HID;
    const int n  = (z == 0) ? BATCH * SEQ * HID : HID * HID;
    int idx = (blockIdx.x * 256 + threadIdx.x) * 16;
    if (idx < n) {
#pragma unroll
        for (int u = 0; u < 2; ++u) {
            float4 v0 = *(const float4*)(src + idx + u * 8);
            float4 v1 = *(const float4*)(src + idx + u * 8 + 4);
            uint4 hv;
            hv.x = h2u(__floats2half2_rn(v0.x, v0.y));
            hv.y = h2u(__floats2half2_rn(v0.z, v0.w));
            hv.z = h2u(__floats2half2_rn(v1.x, v1.y));
            hv.w = h2u(__floats2half2_rn(v1.z, v1.w));
            *(uint4*)&dst[idx + u * 8] = hv;
        }
    }
}

// ============================================================================
// QKV projection: fp16 in/out, 3-stage cp.async ring, ONE barrier per k-tile.
// BM=128, BN=128, BK=64. 256 threads, warps 4(M) x 2(N). 2 CTAs/SM.
// ============================================================================
#define QS 72
#define QKV_SMEM_BYTES (6 * 9216 * 2)

__global__ void __launch_bounds__(256, 2) qkv_kernel(
    const float* __restrict__ bq, const float* __restrict__ bk,
    const float* __restrict__ bv)
{
    const int z = blockIdx.z;
    const __half* Wg  = g_wh + (size_t)z * HID * HID;
    const float* bias = (z == 0) ? bq : (z == 1) ? bk : bv;
    __half* out       = (z == 0) ? g_q : (z == 1) ? g_k : g_v;

    extern __shared__ __half smq[];
    const int tid  = threadIdx.x;
    const int lane = tid & 31;
    const int warp = tid >> 5;
    const int wm = warp >> 1;
    const int wn = warp & 1;
    const int g  = lane >> 2;
    const int t  = lane & 3;
    const int jj = lane >> 3;
    const int rr = lane & 7;
    const int m0 = blockIdx.y * 128;
    const int n0 = blockIdx.x * 128;

    const int row = tid >> 3;
    const int c8  = (tid & 7) * 8;

    float acc[2][8][4];
#pragma unroll
    for (int mt = 0; mt < 2; ++mt)
#pragma unroll
        for (int nt = 0; nt < 8; ++nt)
#pragma unroll
            for (int r = 0; r < 4; ++r) acc[mt][nt][r] = 0.0f;

    // Prologue: issue k-tiles 0,1
#pragma unroll
    for (int s = 0; s < 2; ++s) {
#pragma unroll
        for (int i = 0; i < 4; ++i) {
            int rw = row + i * 32;
            cp_async16(&smq[s * 9216 + rw * QS + c8],
                       g_xh + (size_t)(m0 + rw) * HID + s * 64 + c8);
            cp_async16(&smq[27648 + s * 9216 + rw * QS + c8],
                       Wg + (size_t)(n0 + rw) * HID + s * 64 + c8);
        }
        CP_COMMIT();
    }

    for (int kt = 0; kt < 16; ++kt) {
        if (kt < 15) { CP_WAIT(1); } else { CP_WAIT(0); }
        __syncthreads();

        if (kt + 2 < 16) {
            int ns = (kt + 2) % 3;
#pragma unroll
            for (int i = 0; i < 4; ++i) {
                int rw = row + i * 32;
                cp_async16(&smq[ns * 9216 + rw * QS + c8],
                           g_xh + (size_t)(m0 + rw) * HID + (kt + 2) * 64 + c8);
                cp_async16(&smq[27648 + ns * 9216 + rw * QS + c8],
                           Wg + (size_t)(n0 + rw) * HID + (kt + 2) * 64 + c8);
            }
            CP_COMMIT();
        }

        int buf = kt % 3;
        const __half* Xh = smq + buf * 9216;
        const __half* Wh = smq + 27648 + buf * 9216;

#pragma unroll
        for (int ks = 0; ks < 4; ++ks) {
            uint32_t a[2][4];
#pragma unroll
            for (int mt = 0; mt < 2; ++mt) {
                const __half* p = Xh + (wm * 32 + mt * 16 + (jj & 1) * 8 + rr) * QS
                                + ks * 16 + (jj >> 1) * 8;
                ldsm_x4((uint32_t)__cvta_generic_to_shared(p), a[mt]);
            }
            uint32_t bfr[4][4];
#pragma unroll
            for (int ntp = 0; ntp < 4; ++ntp) {
                const __half* p = Wh + (wn * 64 + ntp * 16 + (jj >> 1) * 8 + rr) * QS
                                + ks * 16 + (jj & 1) * 8;
                ldsm_x4((uint32_t)__cvta_generic_to_shared(p), bfr[ntp]);
            }
#pragma unroll
            for (int mt = 0; mt < 2; ++mt)
#pragma unroll
                for (int ntp = 0; ntp < 4; ++ntp) {
                    mma16(acc[mt][2 * ntp + 0], a[mt], &bfr[ntp][0]);
                    mma16(acc[mt][2 * ntp + 1], a[mt], &bfr[ntp][2]);
                }
        }
    }

#pragma unroll
    for (int mt = 0; mt < 2; ++mt) {
#pragma unroll
        for (int nt = 0; nt < 8; ++nt) {
            int col = n0 + wn * 64 + nt * 8 + 2 * t;
            int hh = col >> 6;
            int d  = col & 63;
            float b0 = bias[col];
            float b1 = bias[col + 1];
#pragma unroll
            for (int half = 0; half < 2; ++half) {
                int m = m0 + wm * 32 + mt * 16 + g + half * 8;
                int bb = m >> 11;
                int s = m & 2047;
                __half2 hv = __floats2half2_rn(acc[mt][nt][half * 2 + 0] + b0,
                                               acc[mt][nt][half * 2 + 1] + b1);
                *(__half2*)&out[(((size_t)bb * NHEADS + hh) * SEQ + s) * HDIM + d] = hv;
            }
        }
    }
}

// ============================================================================
// fp16 flash attention (exact Round-7 version, known-good):
// 3-stage cp.async K/V ring, one barrier per tile, max-free softmax with
// ex2.approx.f16x2, ones-MMA lsum, register-resident P. 2 CTAs/SM.
// ============================================================================
#define HS 72
#define ATTN_MASK_BYTE 73728
#define ATTN_SMEM_BYTES (ATTN_MASK_BYTE + 3 * 64 * 4)

__global__ void __launch_bounds__(256, 2) attn_kernel(
    const float* __restrict__ mask, float* __restrict__ out)
{
    extern __shared__ __half smh[];
    __half* Qh = smh;
    float* mskb = (float*)((char*)smh + ATTN_MASK_BYTE);

    const int tid = threadIdx.x;
    const int lane = tid & 31;
    const int warp = tid >> 5;
    const int g  = lane >> 2;
    const int t  = lane & 3;
    const int jj = lane >> 3;
    const int rr = lane & 7;
    const int wr = warp * 16;

    const int bh = blockIdx.y;
    const int b = bh >> 4;
    const int h = bh & 15;
    const int q0 = blockIdx.x * 128;

    const __half* qptr = g_q + (size_t)bh * SEQ * HDIM;
    const __half* kptr = g_k + (size_t)bh * SEQ * HDIM;
    const __half* vptr = g_v + (size_t)bh * SEQ * HDIM;

    const int row = tid >> 3;
    const int c8  = (tid & 7) * 8;

    // ---- Stage Q ----
#pragma unroll
    for (int i = 0; i < 4; ++i) {
        int rw = row + i * 32;
        *(uint4*)&Qh[rw * HS + c8] = *(const uint4*)(qptr + (size_t)(q0 + rw) * HDIM + c8);
    }

    // ---- Issue K/V/mask tiles 0,1 ----
#pragma unroll
    for (int s = 0; s < 2; ++s) {
#pragma unroll
        for (int i = 0; i < 2; ++i) {
            int rw = row + i * 32;
            cp_async16(&smh[9216 + s * 4608 + rw * HS + c8],
                       kptr + (size_t)(s * 64 + rw) * HDIM + c8);
            cp_async16(&smh[23040 + s * 4608 + rw * HS + c8],
                       vptr + (size_t)(s * 64 + rw) * HDIM + c8);
        }
        if (tid < 16)
            cp_async16(&mskb[s * 64 + tid * 4], mask + (size_t)b * SEQ + s * 64 + tid * 4);
        CP_COMMIT();
    }
    __syncthreads();

    // ---- Q fragments (once) ----
    uint32_t qa[4][4];
#pragma unroll
    for (int ks = 0; ks < 4; ++ks) {
        const __half* p = Qh + (wr + (jj & 1) * 8 + rr) * HS + ks * 16 + (jj >> 1) * 8;
        ldsm_x4((uint32_t)__cvta_generic_to_shared(p), qa[ks]);
    }

    float oacc[8][4];
#pragma unroll
    for (int nt = 0; nt < 8; ++nt)
#pragma unroll
        for (int r = 0; r < 4; ++r) oacc[nt][r] = 0.0f;
    float lacc[4] = {0.0f, 0.0f, 0.0f, 0.0f};
    const uint32_t ONE2 = 0x3C003C00u;
    const uint32_t ones_b[2] = {ONE2, ONE2};

    int stage = 0;
    for (int j = 0; j < 32; ++j) {
        if (j < 31) { CP_WAIT(1); } else { CP_WAIT(0); }
        __syncthreads();

        if (j + 2 < 32) {
            int ns = stage + 2; if (ns >= 3) ns -= 3;
#pragma unroll
            for (int i = 0; i < 2; ++i) {
                int rw = row + i * 32;
                cp_async16(&smh[9216 + ns * 4608 + rw * HS + c8],
                           kptr + (size_t)((j + 2) * 64 + rw) * HDIM + c8);
                cp_async16(&smh[23040 + ns * 4608 + rw * HS + c8],
                           vptr + (size_t)((j + 2) * 64 + rw) * HDIM + c8);
            }
            if (tid < 16)
                cp_async16(&mskb[ns * 64 + tid * 4],
                           mask + (size_t)b * SEQ + (j + 2) * 64 + tid * 4);
            CP_COMMIT();
        }

        const __half* Kb = smh + 9216 + stage * 4608;
        const __half* Vb = smh + 23040 + stage * 4608;
        const float* mk = mskb + stage * 64;

        // ---- S = Q K^T ----
        float sacc[8][4];
#pragma unroll
        for (int nt = 0; nt < 8; ++nt)
#pragma unroll
            for (int r = 0; r < 4; ++r) sacc[nt][r] = 0.0f;

#pragma unroll
        for (int ks = 0; ks < 4; ++ks) {
#pragma unroll
            for (int ntp = 0; ntp < 4; ++ntp) {
                uint32_t bb[4];
                const __half* p = Kb + (ntp * 16 + (jj >> 1) * 8 + rr) * HS
                                + ks * 16 + (jj & 1) * 8;
                ldsm_x4((uint32_t)__cvta_generic_to_shared(p), bb);
                mma16(sacc[2 * ntp + 0], qa[ks], &bb[0]);
                mma16(sacc[2 * ntp + 1], qa[ks], &bb[2]);
            }
        }

        // ---- softmax: p = 2^((s/8 + m)*log2e), fp16x2 exp ----
        uint32_t ph[8][2];
#pragma unroll
        for (int nt = 0; nt < 8; ++nt) {
            int col = nt * 8 + 2 * t;
            float m0f = mk[col] * LOG2E;
            float m1f = mk[col + 1] * LOG2E;
            const float cc = 0.125f * LOG2E;
            float y0 = fmaf(sacc[nt][0], cc, m0f);
            float y1 = fmaf(sacc[nt][1], cc, m1f);
            float y2 = fmaf(sacc[nt][2], cc, m0f);
            float y3 = fmaf(sacc[nt][3], cc, m1f);
            uint32_t a01 = h2u(__floats2half2_rn(y0, y1));
            uint32_t a23 = h2u(__floats2half2_rn(y2, y3));
            asm("ex2.approx.f16x2 %0, %1;" : "=r"(ph[nt][0]) : "r"(a01));
            asm("ex2.approx.f16x2 %0, %1;" : "=r"(ph[nt][1]) : "r"(a23));
        }

        // ---- O += P V ; lsum += P 1 ----
#pragma unroll
        for (int ks = 0; ks < 4; ++ks) {
            uint32_t pa[4] = { ph[2 * ks][0], ph[2 * ks][1],
                               ph[2 * ks + 1][0], ph[2 * ks + 1][1] };
            mma16(lacc, pa, ones_b);
#pragma unroll
            for (int ntp = 0; ntp < 4; ++ntp) {
                uint32_t bb[4];
                const __half* p = Vb + (ks * 16 + (jj & 1) * 8 + rr) * HS
                                + ntp * 16 + (jj >> 1) * 8;
                ldsm_x4_t((uint32_t)__cvta_generic_to_shared(p), bb);
                mma16(oacc[2 * ntp + 0], pa, &bb[0]);
                mma16(oacc[2 * ntp + 1], pa, &bb[2]);
            }
        }

        ++stage; if (stage == 3) stage = 0;
    }

    // ---- Epilogue: lacc c0/c2 are complete row sums ----
    float inv0 = 1.0f / lacc[0];
    float inv1 = 1.0f / lacc[2];

    float* orow0 = out + ((size_t)b * SEQ + q0 + wr + g) * HID + h * HDIM;
    float* orow1 = orow0 + (size_t)8 * HID;
#pragma unroll
    for (int nt = 0; nt < 8; ++nt) {
        int col = nt * 8 + 2 * t;
        float2 v0 = { oacc[nt][0] * inv0, oacc[nt][1] * inv0 };
        float2 v1 = { oacc[nt][2] * inv1, oacc[nt][3] * inv1 };
        *(float2*)&orow0[col] = v0;
        *(float2*)&orow1[col] = v1;
    }
}

extern "C" void kernel_launch(void* const* d_in, const int* in_sizes, int n_in,
                              void* d_out, int out_size)
{
    const float* hs   = (const float*)d_in[0];
    const float* mask = (const float*)d_in[1];
    const float* Wq   = (const float*)d_in[2];
    const float* bq   = (const float*)d_in[3];
    const float* Wk   = (const float*)d_in[4];
    const float* bk   = (const float*)d_in[5];
    const float* Wv   = (const float*)d_in[6];
    const float* bv   = (const float*)d_in[7];
    float* out = (float*)d_out;

    dim3 gc(1024, 4);
    convert_kernel<<<gc, 256>>>(hs, Wq, Wk, Wv);

    cudaFuncSetAttribute(qkv_kernel, cudaFuncAttributeMaxDynamicSharedMemorySize,
                         QKV_SMEM_BYTES);
    dim3 gq(HID / 128, (BATCH * SEQ) / 128, 3);
    qkv_kernel<<<gq, 256, QKV_SMEM_BYTES>>>(bq, bk, bv);

    cudaFuncSetAttribute(attn_kernel, cudaFuncAttributeMaxDynamicSharedMemorySize,
                         ATTN_SMEM_BYTES);
    dim3 ga(SEQ / 128, BATCH * NHEADS);
    attn_kernel<<<ga, 256, ATTN_SMEM_BYTES>>>(mask, out);
}

// round 11
// speedup vs baseline: 1.1207x; 1.1207x over previous
#include <cuda_runtime.h>
#include <cuda_fp16.h>
#include <cstdint>

#define BATCH 2
#define SEQ 2048
#define HID 1024
#define NHEADS 16
#define HDIM 64

// fp16 scratch (device globals: allocation-free).
__device__ __align__(16) __half g_xh[BATCH * SEQ * HID];
__device__ __align__(16) __half g_wh[3 * HID * HID];
__device__ __align__(16) __half g_q[BATCH * NHEADS * SEQ * HDIM];
__device__ __align__(16) __half g_k[BATCH * NHEADS * SEQ * HDIM];
__device__ __align__(16) __half g_v[BATCH * NHEADS * SEQ * HDIM];

__device__ __forceinline__ uint32_t h2u(__half2 h) {
    return *reinterpret_cast<uint32_t*>(&h);
}

__device__ __forceinline__ void ldsm_x4(uint32_t addr, uint32_t r[4]) {
    asm volatile("ldmatrix.sync.aligned.m8n8.x4.shared.b16 {%0,%1,%2,%3}, [%4];"
        : "=r"(r[0]), "=r"(r[1]), "=r"(r[2]), "=r"(r[3]) : "r"(addr));
}
__device__ __forceinline__ void ldsm_x4_t(uint32_t addr, uint32_t r[4]) {
    asm volatile("ldmatrix.sync.aligned.m8n8.x4.trans.shared.b16 {%0,%1,%2,%3}, [%4];"
        : "=r"(r[0]), "=r"(r[1]), "=r"(r[2]), "=r"(r[3]) : "r"(addr));
}

__device__ __forceinline__ void mma16(float c[4], const uint32_t a[4], const uint32_t b[2]) {
    asm volatile(
        "mma.sync.aligned.m16n8k16.row.col.f32.f16.f16.f32 "
        "{%0,%1,%2,%3}, {%4,%5,%6,%7}, {%8,%9}, {%0,%1,%2,%3};\n"
        : "+f"(c[0]), "+f"(c[1]), "+f"(c[2]), "+f"(c[3])
        : "r"(a[0]), "r"(a[1]), "r"(a[2]), "r"(a[3]), "r"(b[0]), "r"(b[1]));
}

__device__ __forceinline__ void cp_async16(void* smem_dst, const void* gmem_src) {
    uint32_t s = (uint32_t)__cvta_generic_to_shared(smem_dst);
    asm volatile("cp.async.ca.shared.global [%0], [%1], 16;" :: "r"(s), "l"(gmem_src));
}
#define CP_COMMIT() asm volatile("cp.async.commit_group;" ::: "memory")
#define CP_WAIT(n)  asm volatile("cp.async.wait_group %0;" :: "n"(n) : "memory")

#define LOG2E 1.44269504f

// ============================================================================
// Convert fp32 -> fp16 (X and three W). 8 elems/thread (R7 version, 10.0us).
// ============================================================================
__global__ void __launch_bounds__(256) convert_kernel(
    const float* __restrict__ X,
    const float* __restrict__ Wq, const float* __restrict__ Wk,
    const float* __restrict__ Wv)
{
    const int z = blockIdx.y;
    const float* src = (z == 0) ? X : (z == 1) ? Wq : (z == 2) ? Wk : Wv;
    __half* dst = (z == 0) ? g_xh : g_wh + (size_t)(z - 1) * HID * HID;
    const int n  = (z == 0) ? BATCH * SEQ * HID : HID * HID;
    int idx = (blockIdx.x * 256 + threadIdx.x) * 8;
    if (idx < n) {
        float4 v0 = *(const float4*)(src + idx);
        float4 v1 = *(const float4*)(src + idx + 4);
        uint4 hv;
        hv.x = h2u(__floats2half2_rn(v0.x, v0.y));
        hv.y = h2u(__floats2half2_rn(v0.z, v0.w));
        hv.z = h2u(__floats2half2_rn(v1.x, v1.y));
        hv.w = h2u(__floats2half2_rn(v1.z, v1.w));
        *(uint4*)&dst[idx] = hv;
    }
}

// ============================================================================
// QKV projection (EXACT R7 version, known-good): fp16 in/out, cp.async
// 2-stage, 2 CTAs/SM. BM=128, BN=128, BK=64. 256 threads, warps 4(M) x 2(N).
// ============================================================================
#define QS 72
#define QKV_SMEM_BYTES (4 * 128 * QS * 2)

__global__ void __launch_bounds__(256, 2) qkv_kernel(
    const float* __restrict__ bq, const float* __restrict__ bk,
    const float* __restrict__ bv)
{
    const int z = blockIdx.z;
    const __half* Wg  = g_wh + (size_t)z * HID * HID;
    const float* bias = (z == 0) ? bq : (z == 1) ? bk : bv;
    __half* out       = (z == 0) ? g_q : (z == 1) ? g_k : g_v;

    extern __shared__ __half smq[];
    const int tid  = threadIdx.x;
    const int lane = tid & 31;
    const int warp = tid >> 5;
    const int wm = warp >> 1;
    const int wn = warp & 1;
    const int g  = lane >> 2;
    const int t  = lane & 3;
    const int jj = lane >> 3;
    const int rr = lane & 7;
    const int m0 = blockIdx.y * 128;
    const int n0 = blockIdx.x * 128;

    const int row = tid >> 3;
    const int c8  = (tid & 7) * 8;

    float acc[2][8][4];
#pragma unroll
    for (int mt = 0; mt < 2; ++mt)
#pragma unroll
        for (int nt = 0; nt < 8; ++nt)
#pragma unroll
            for (int r = 0; r < 4; ++r) acc[mt][nt][r] = 0.0f;

#pragma unroll
    for (int i = 0; i < 4; ++i) {
        int rw = row + i * 32;
        cp_async16(&smq[rw * QS + c8], g_xh + (size_t)(m0 + rw) * HID + c8);
        cp_async16(&smq[18432 + rw * QS + c8], Wg + (size_t)(n0 + rw) * HID + c8);
    }
    CP_COMMIT();

    for (int kt = 0; kt < 16; ++kt) {
        int buf = kt & 1;
        if (kt < 15) {
            int nb = buf ^ 1;
#pragma unroll
            for (int i = 0; i < 4; ++i) {
                int rw = row + i * 32;
                cp_async16(&smq[nb * 9216 + rw * QS + c8],
                           g_xh + (size_t)(m0 + rw) * HID + (kt + 1) * 64 + c8);
                cp_async16(&smq[18432 + nb * 9216 + rw * QS + c8],
                           Wg + (size_t)(n0 + rw) * HID + (kt + 1) * 64 + c8);
            }
            CP_COMMIT();
            CP_WAIT(1);
        } else {
            CP_WAIT(0);
        }
        __syncthreads();

        const __half* Xh = smq + buf * 9216;
        const __half* Wh = smq + 18432 + buf * 9216;

#pragma unroll
        for (int ks = 0; ks < 4; ++ks) {
            uint32_t a[2][4];
#pragma unroll
            for (int mt = 0; mt < 2; ++mt) {
                const __half* p = Xh + (wm * 32 + mt * 16 + (jj & 1) * 8 + rr) * QS
                                + ks * 16 + (jj >> 1) * 8;
                ldsm_x4((uint32_t)__cvta_generic_to_shared(p), a[mt]);
            }
            uint32_t bfr[4][4];
#pragma unroll
            for (int ntp = 0; ntp < 4; ++ntp) {
                const __half* p = Wh + (wn * 64 + ntp * 16 + (jj >> 1) * 8 + rr) * QS
                                + ks * 16 + (jj & 1) * 8;
                ldsm_x4((uint32_t)__cvta_generic_to_shared(p), bfr[ntp]);
            }
#pragma unroll
            for (int mt = 0; mt < 2; ++mt)
#pragma unroll
                for (int ntp = 0; ntp < 4; ++ntp) {
                    mma16(acc[mt][2 * ntp + 0], a[mt], &bfr[ntp][0]);
                    mma16(acc[mt][2 * ntp + 1], a[mt], &bfr[ntp][2]);
                }
        }
        __syncthreads();
    }

#pragma unroll
    for (int mt = 0; mt < 2; ++mt) {
#pragma unroll
        for (int nt = 0; nt < 8; ++nt) {
            int col = n0 + wn * 64 + nt * 8 + 2 * t;
            int hh = col >> 6;
            int d  = col & 63;
            float b0 = bias[col];
            float b1 = bias[col + 1];
#pragma unroll
            for (int half = 0; half < 2; ++half) {
                int m = m0 + wm * 32 + mt * 16 + g + half * 8;
                int bb = m >> 11;
                int s = m & 2047;
                __half2 hv = __floats2half2_rn(acc[mt][nt][half * 2 + 0] + b0,
                                               acc[mt][nt][half * 2 + 1] + b1);
                *(__half2*)&out[(((size_t)bb * NHEADS + hh) * SEQ + s) * HDIM + d] = hv;
            }
        }
    }
}

// ============================================================================
// fp16 flash attention, M=32 rows per warp (BM=256, grid 256, 1 CTA/SM):
// B-fragments (K and V) loaded once per k-step and reused across BOTH
// m-subtiles -> smem crossbar traffic per q-row halved vs M=16.
// 3-stage cp.async ring, max-free softmax (ex2.f16x2), ones-MMA lsum.
// smem: Q 256x72 | K stages 3x64x72 | V stages 3x64x72 | mask 3x64 f32.
// ============================================================================
#define HS 72
#define AQ_H 18432              // Q halves (256*72)
#define AK_H(s) (18432 + (s) * 4608)
#define AV_H(s) (32256 + (s) * 4608)
#define ATTN_MASK_BYTE 92160
#define ATTN_SMEM_BYTES (ATTN_MASK_BYTE + 3 * 64 * 4)

__global__ void __launch_bounds__(256, 1) attn_kernel(
    const float* __restrict__ mask, float* __restrict__ out)
{
    extern __shared__ __half smh[];
    __half* Qh = smh;
    float* mskb = (float*)((char*)smh + ATTN_MASK_BYTE);

    const int tid = threadIdx.x;
    const int lane = tid & 31;
    const int warp = tid >> 5;
    const int g  = lane >> 2;
    const int t  = lane & 3;
    const int jj = lane >> 3;
    const int rr = lane & 7;
    const int wr = warp * 32;           // 32 q-rows per warp

    const int bh = blockIdx.y;
    const int b = bh >> 4;
    const int h = bh & 15;
    const int q0 = blockIdx.x * 256;    // 256 q-rows per CTA

    const __half* qptr = g_q + (size_t)bh * SEQ * HDIM;
    const __half* kptr = g_k + (size_t)bh * SEQ * HDIM;
    const __half* vptr = g_v + (size_t)bh * SEQ * HDIM;

    const int row = tid >> 3;
    const int c8  = (tid & 7) * 8;

    // ---- Stage Q (256 x 64 fp16) ----
#pragma unroll
    for (int i = 0; i < 8; ++i) {
        int rw = row + i * 32;
        *(uint4*)&Qh[rw * HS + c8] = *(const uint4*)(qptr + (size_t)(q0 + rw) * HDIM + c8);
    }

    // ---- Issue K/V/mask tiles 0,1 ----
#pragma unroll
    for (int s = 0; s < 2; ++s) {
#pragma unroll
        for (int i = 0; i < 2; ++i) {
            int rw = row + i * 32;
            cp_async16(&smh[AK_H(s) + rw * HS + c8],
                       kptr + (size_t)(s * 64 + rw) * HDIM + c8);
            cp_async16(&smh[AV_H(s) + rw * HS + c8],
                       vptr + (size_t)(s * 64 + rw) * HDIM + c8);
        }
        if (tid < 16)
            cp_async16(&mskb[s * 64 + tid * 4], mask + (size_t)b * SEQ + s * 64 + tid * 4);
        CP_COMMIT();
    }
    __syncthreads();

    // ---- Q fragments (2 m-subtiles x 4 k-steps) ----
    uint32_t qa[2][4][4];
#pragma unroll
    for (int mt = 0; mt < 2; ++mt)
#pragma unroll
        for (int ks = 0; ks < 4; ++ks) {
            const __half* p = Qh + (wr + mt * 16 + (jj & 1) * 8 + rr) * HS
                            + ks * 16 + (jj >> 1) * 8;
            ldsm_x4((uint32_t)__cvta_generic_to_shared(p), qa[mt][ks]);
        }

    float oacc[2][8][4];
#pragma unroll
    for (int mt = 0; mt < 2; ++mt)
#pragma unroll
        for (int nt = 0; nt < 8; ++nt)
#pragma unroll
            for (int r = 0; r < 4; ++r) oacc[mt][nt][r] = 0.0f;
    float lacc[2][4] = {{0.0f, 0.0f, 0.0f, 0.0f}, {0.0f, 0.0f, 0.0f, 0.0f}};
    const uint32_t ONE2 = 0x3C003C00u;
    const uint32_t ones_b[2] = {ONE2, ONE2};

    int stage = 0;
    for (int j = 0; j < 32; ++j) {
        if (j < 31) { CP_WAIT(1); } else { CP_WAIT(0); }
        __syncthreads();

        if (j + 2 < 32) {
            int ns = stage + 2; if (ns >= 3) ns -= 3;
#pragma unroll
            for (int i = 0; i < 2; ++i) {
                int rw = row + i * 32;
                cp_async16(&smh[AK_H(ns) + rw * HS + c8],
                           kptr + (size_t)((j + 2) * 64 + rw) * HDIM + c8);
                cp_async16(&smh[AV_H(ns) + rw * HS + c8],
                           vptr + (size_t)((j + 2) * 64 + rw) * HDIM + c8);
            }
            if (tid < 16)
                cp_async16(&mskb[ns * 64 + tid * 4],
                           mask + (size_t)b * SEQ + (j + 2) * 64 + tid * 4);
            CP_COMMIT();
        }

        const __half* Kb = smh + AK_H(stage);
        const __half* Vb = smh + AV_H(stage);
        const float* mk = mskb + stage * 64;

        // ---- S = Q K^T : 32 x 64 per warp; K-frags shared across m-subtiles ----
        float sacc[2][8][4];
#pragma unroll
        for (int mt = 0; mt < 2; ++mt)
#pragma unroll
            for (int nt = 0; nt < 8; ++nt)
#pragma unroll
                for (int r = 0; r < 4; ++r) sacc[mt][nt][r] = 0.0f;

#pragma unroll
        for (int ks = 0; ks < 4; ++ks) {
#pragma unroll
            for (int ntp = 0; ntp < 4; ++ntp) {
                uint32_t bb[4];
                const __half* p = Kb + (ntp * 16 + (jj >> 1) * 8 + rr) * HS
                                + ks * 16 + (jj & 1) * 8;
                ldsm_x4((uint32_t)__cvta_generic_to_shared(p), bb);
#pragma unroll
                for (int mt = 0; mt < 2; ++mt) {
                    mma16(sacc[mt][2 * ntp + 0], qa[mt][ks], &bb[0]);
                    mma16(sacc[mt][2 * ntp + 1], qa[mt][ks], &bb[2]);
                }
            }
        }

        // ---- softmax: p = 2^((s/8 + m)*log2e) per m-subtile ----
        uint32_t ph[2][8][2];
#pragma unroll
        for (int mt = 0; mt < 2; ++mt) {
#pragma unroll
            for (int nt = 0; nt < 8; ++nt) {
                int col = nt * 8 + 2 * t;
                float m0f = mk[col] * LOG2E;
                float m1f = mk[col + 1] * LOG2E;
                const float cc = 0.125f * LOG2E;
                float y0 = fmaf(sacc[mt][nt][0], cc, m0f);
                float y1 = fmaf(sacc[mt][nt][1], cc, m1f);
                float y2 = fmaf(sacc[mt][nt][2], cc, m0f);
                float y3 = fmaf(sacc[mt][nt][3], cc, m1f);
                uint32_t a01 = h2u(__floats2half2_rn(y0, y1));
                uint32_t a23 = h2u(__floats2half2_rn(y2, y3));
                asm("ex2.approx.f16x2 %0, %1;" : "=r"(ph[mt][nt][0]) : "r"(a01));
                asm("ex2.approx.f16x2 %0, %1;" : "=r"(ph[mt][nt][1]) : "r"(a23));
            }
        }

        // ---- O += P V ; lsum += P 1 : V-frags shared across m-subtiles ----
#pragma unroll
        for (int ks = 0; ks < 4; ++ks) {
            uint32_t pa[2][4];
#pragma unroll
            for (int mt = 0; mt < 2; ++mt) {
                pa[mt][0] = ph[mt][2 * ks][0];
                pa[mt][1] = ph[mt][2 * ks][1];
                pa[mt][2] = ph[mt][2 * ks + 1][0];
                pa[mt][3] = ph[mt][2 * ks + 1][1];
                mma16(lacc[mt], pa[mt], ones_b);
            }
#pragma unroll
            for (int ntp = 0; ntp < 4; ++ntp) {
                uint32_t bb[4];
                const __half* p = Vb + (ks * 16 + (jj & 1) * 8 + rr) * HS
                                + ntp * 16 + (jj >> 1) * 8;
                ldsm_x4_t((uint32_t)__cvta_generic_to_shared(p), bb);
#pragma unroll
                for (int mt = 0; mt < 2; ++mt) {
                    mma16(oacc[mt][2 * ntp + 0], pa[mt], &bb[0]);
                    mma16(oacc[mt][2 * ntp + 1], pa[mt], &bb[2]);
                }
            }
        }

        ++stage; if (stage == 3) stage = 0;
    }

    // ---- Epilogue ----
#pragma unroll
    for (int mt = 0; mt < 2; ++mt) {
        float inv0 = 1.0f / lacc[mt][0];
        float inv1 = 1.0f / lacc[mt][2];
        float* orow0 = out + ((size_t)b * SEQ + q0 + wr + mt * 16 + g) * HID + h * HDIM;
        float* orow1 = orow0 + (size_t)8 * HID;
#pragma unroll
        for (int nt = 0; nt < 8; ++nt) {
            int col = nt * 8 + 2 * t;
            float2 v0 = { oacc[mt][nt][0] * inv0, oacc[mt][nt][1] * inv0 };
            float2 v1 = { oacc[mt][nt][2] * inv1, oacc[mt][nt][3] * inv1 };
            *(float2*)&orow0[col] = v0;
            *(float2*)&orow1[col] = v1;
        }
    }
}

extern "C" void kernel_launch(void* const* d_in, const int* in_sizes, int n_in,
                              void* d_out, int out_size)
{
    const float* hs   = (const float*)d_in[0];
    const float* mask = (const float*)d_in[1];
    const float* Wq   = (const float*)d_in[2];
    const float* bq   = (const float*)d_in[3];
    const float* Wk   = (const float*)d_in[4];
    const float* bk   = (const float*)d_in[5];
    const float* Wv   = (const float*)d_in[6];
    const float* bv   = (const float*)d_in[7];
    float* out = (float*)d_out;

    dim3 gc(2048, 4);
    convert_kernel<<<gc, 256>>>(hs, Wq, Wk, Wv);

    cudaFuncSetAttribute(qkv_kernel, cudaFuncAttributeMaxDynamicSharedMemorySize,
                         QKV_SMEM_BYTES);
    dim3 gq(HID / 128, (BATCH * SEQ) / 128, 3);
    qkv_kernel<<<gq, 256, QKV_SMEM_BYTES>>>(bq, bk, bv);

    cudaFuncSetAttribute(attn_kernel, cudaFuncAttributeMaxDynamicSharedMemorySize,
                         ATTN_SMEM_BYTES);
    dim3 ga(SEQ / 256, BATCH * NHEADS);   // (8, 32) = 256 CTAs
    attn_kernel<<<ga, 256, ATTN_SMEM_BYTES>>>(mask, out);
}

// round 12
// speedup vs baseline: 1.1511x; 1.0272x over previous
#include <cuda_runtime.h>
#include <cuda_fp16.h>
#include <cstdint>

#define BATCH 2
#define SEQ 2048
#define HID 1024
#define NHEADS 16
#define HDIM 64

// fp16 scratch (device globals: allocation-free).
__device__ __align__(16) __half g_xh[BATCH * SEQ * HID];
__device__ __align__(16) __half g_wh[3 * HID * HID];
__device__ __align__(16) __half g_q[BATCH * NHEADS * SEQ * HDIM];
__device__ __align__(16) __half g_k[BATCH * NHEADS * SEQ * HDIM];
__device__ __align__(16) __half g_v[BATCH * NHEADS * SEQ * HDIM];

__device__ __forceinline__ uint32_t h2u(__half2 h) {
    return *reinterpret_cast<uint32_t*>(&h);
}

__device__ __forceinline__ void ldsm_x4(uint32_t addr, uint32_t r[4]) {
    asm volatile("ldmatrix.sync.aligned.m8n8.x4.shared.b16 {%0,%1,%2,%3}, [%4];"
        : "=r"(r[0]), "=r"(r[1]), "=r"(r[2]), "=r"(r[3]) : "r"(addr));
}
__device__ __forceinline__ void ldsm_x4_t(uint32_t addr, uint32_t r[4]) {
    asm volatile("ldmatrix.sync.aligned.m8n8.x4.trans.shared.b16 {%0,%1,%2,%3}, [%4];"
        : "=r"(r[0]), "=r"(r[1]), "=r"(r[2]), "=r"(r[3]) : "r"(addr));
}

__device__ __forceinline__ void mma16(float c[4], const uint32_t a[4], const uint32_t b[2]) {
    asm volatile(
        "mma.sync.aligned.m16n8k16.row.col.f32.f16.f16.f32 "
        "{%0,%1,%2,%3}, {%4,%5,%6,%7}, {%8,%9}, {%0,%1,%2,%3};\n"
        : "+f"(c[0]), "+f"(c[1]), "+f"(c[2]), "+f"(c[3])
        : "r"(a[0]), "r"(a[1]), "r"(a[2]), "r"(a[3]), "r"(b[0]), "r"(b[1]));
}

__device__ __forceinline__ void cp_async16(void* smem_dst, const void* gmem_src) {
    uint32_t s = (uint32_t)__cvta_generic_to_shared(smem_dst);
    asm volatile("cp.async.ca.shared.global [%0], [%1], 16;" :: "r"(s), "l"(gmem_src));
}
#define CP_COMMIT() asm volatile("cp.async.commit_group;" ::: "memory")
#define CP_WAIT(n)  asm volatile("cp.async.wait_group %0;" :: "n"(n) : "memory")

#define LOG2E 1.44269504f

// ============================================================================
// Convert fp32 -> fp16 (X and three W). 8 elems/thread.
// ============================================================================
__global__ void __launch_bounds__(256) convert_kernel(
    const float* __restrict__ X,
    const float* __restrict__ Wq, const float* __restrict__ Wk,
    const float* __restrict__ Wv)
{
    const int z = blockIdx.y;
    const float* src = (z == 0) ? X : (z == 1) ? Wq : (z == 2) ? Wk : Wv;
    __half* dst = (z == 0) ? g_xh : g_wh + (size_t)(z - 1) * HID * HID;
    const int n  = (z == 0) ? BATCH * SEQ * HID : HID * HID;
    int idx = (blockIdx.x * 256 + threadIdx.x) * 8;
    if (idx < n) {
        float4 v0 = *(const float4*)(src + idx);
        float4 v1 = *(const float4*)(src + idx + 4);
        uint4 hv;
        hv.x = h2u(__floats2half2_rn(v0.x, v0.y));
        hv.y = h2u(__floats2half2_rn(v0.z, v0.w));
        hv.z = h2u(__floats2half2_rn(v1.x, v1.y));
        hv.w = h2u(__floats2half2_rn(v1.z, v1.w));
        *(uint4*)&dst[idx] = hv;
    }
}

// ============================================================================
// QKV projection, BIG-TILE: BM=256, BN=128, BK=64; warp tile 64x64
// (warps 4(M) x 2(N)), 256 threads, 1 CTA/SM. 2-stage cp.async.
// Per ks: 4 A-LDSM + 4 B-LDSM feed 32 MMAs -> crossbar per output halved.
// smem halves: X0 [0), X1 [18432), W0 [36864), W1 [46080). 110592 B total.
// ============================================================================
#define QS 72
#define QKV_SMEM_BYTES 110592

__global__ void __launch_bounds__(256, 1) qkv_kernel(
    const float* __restrict__ bq, const float* __restrict__ bk,
    const float* __restrict__ bv)
{
    const int z = blockIdx.z;
    const __half* Wg  = g_wh + (size_t)z * HID * HID;
    const float* bias = (z == 0) ? bq : (z == 1) ? bk : bv;
    __half* out       = (z == 0) ? g_q : (z == 1) ? g_k : g_v;

    extern __shared__ __half smq[];
    const int tid  = threadIdx.x;
    const int lane = tid & 31;
    const int warp = tid >> 5;
    const int wm = warp >> 1;          // 0..3 (64 rows each)
    const int wn = warp & 1;           // 0..1 (64 cols each)
    const int g  = lane >> 2;
    const int t  = lane & 3;
    const int jj = lane >> 3;
    const int rr = lane & 7;
    const int m0 = blockIdx.y * 256;
    const int n0 = blockIdx.x * 128;

    const int row = tid >> 3;          // 0..31
    const int c8  = (tid & 7) * 8;

    float acc[4][8][4];
#pragma unroll
    for (int mt = 0; mt < 4; ++mt)
#pragma unroll
        for (int nt = 0; nt < 8; ++nt)
#pragma unroll
            for (int r = 0; r < 4; ++r) acc[mt][nt][r] = 0.0f;

    // Prologue: stage 0 (X 256x64: 8 cp/thread; W 128x64: 4 cp/thread)
#pragma unroll
    for (int i = 0; i < 8; ++i) {
        int rw = row + i * 32;
        cp_async16(&smq[rw * QS + c8], g_xh + (size_t)(m0 + rw) * HID + c8);
    }
#pragma unroll
    for (int i = 0; i < 4; ++i) {
        int rw = row + i * 32;
        cp_async16(&smq[36864 + rw * QS + c8], Wg + (size_t)(n0 + rw) * HID + c8);
    }
    CP_COMMIT();

    for (int kt = 0; kt < 16; ++kt) {
        int buf = kt & 1;
        if (kt < 15) {
            int nb = buf ^ 1;
#pragma unroll
            for (int i = 0; i < 8; ++i) {
                int rw = row + i * 32;
                cp_async16(&smq[nb * 18432 + rw * QS + c8],
                           g_xh + (size_t)(m0 + rw) * HID + (kt + 1) * 64 + c8);
            }
#pragma unroll
            for (int i = 0; i < 4; ++i) {
                int rw = row + i * 32;
                cp_async16(&smq[36864 + nb * 9216 + rw * QS + c8],
                           Wg + (size_t)(n0 + rw) * HID + (kt + 1) * 64 + c8);
            }
            CP_COMMIT();
            CP_WAIT(1);
        } else {
            CP_WAIT(0);
        }
        __syncthreads();

        const __half* Xh = smq + buf * 18432;
        const __half* Wh = smq + 36864 + buf * 9216;

#pragma unroll
        for (int ks = 0; ks < 4; ++ks) {
            uint32_t a[4][4];
#pragma unroll
            for (int mt = 0; mt < 4; ++mt) {
                const __half* p = Xh + (wm * 64 + mt * 16 + (jj & 1) * 8 + rr) * QS
                                + ks * 16 + (jj >> 1) * 8;
                ldsm_x4((uint32_t)__cvta_generic_to_shared(p), a[mt]);
            }
            uint32_t bfr[4][4];
#pragma unroll
            for (int ntp = 0; ntp < 4; ++ntp) {
                const __half* p = Wh + (wn * 64 + ntp * 16 + (jj >> 1) * 8 + rr) * QS
                                + ks * 16 + (jj & 1) * 8;
                ldsm_x4((uint32_t)__cvta_generic_to_shared(p), bfr[ntp]);
            }
#pragma unroll
            for (int mt = 0; mt < 4; ++mt)
#pragma unroll
                for (int ntp = 0; ntp < 4; ++ntp) {
                    mma16(acc[mt][2 * ntp + 0], a[mt], &bfr[ntp][0]);
                    mma16(acc[mt][2 * ntp + 1], a[mt], &bfr[ntp][2]);
                }
        }
        __syncthreads();
    }

    // Epilogue -> fp16 scratch [B, NH, S, HD]
#pragma unroll
    for (int mt = 0; mt < 4; ++mt) {
#pragma unroll
        for (int nt = 0; nt < 8; ++nt) {
            int col = n0 + wn * 64 + nt * 8 + 2 * t;
            int hh = col >> 6;
            int d  = col & 63;
            float b0 = bias[col];
            float b1 = bias[col + 1];
#pragma unroll
            for (int half = 0; half < 2; ++half) {
                int m = m0 + wm * 64 + mt * 16 + g + half * 8;
                int bb = m >> 11;
                int s = m & 2047;
                __half2 hv = __floats2half2_rn(acc[mt][nt][half * 2 + 0] + b0,
                                               acc[mt][nt][half * 2 + 1] + b1);
                *(__half2*)&out[(((size_t)bb * NHEADS + hh) * SEQ + s) * HDIM + d] = hv;
            }
        }
    }
}

// ============================================================================
// fp16 flash attention (EXACT R10 version, known-good 196-total):
// M=32 rows per warp (BM=256, grid 256, 1 CTA/SM), B-frag reuse across
// m-subtiles, 3-stage cp.async ring, max-free softmax (ex2.f16x2),
// ones-MMA lsum.
// ============================================================================
#define HS 72
#define AK_H(s) (18432 + (s) * 4608)
#define AV_H(s) (32256 + (s) * 4608)
#define ATTN_MASK_BYTE 92160
#define ATTN_SMEM_BYTES (ATTN_MASK_BYTE + 3 * 64 * 4)

__global__ void __launch_bounds__(256, 1) attn_kernel(
    const float* __restrict__ mask, float* __restrict__ out)
{
    extern __shared__ __half smh[];
    __half* Qh = smh;
    float* mskb = (float*)((char*)smh + ATTN_MASK_BYTE);

    const int tid = threadIdx.x;
    const int lane = tid & 31;
    const int warp = tid >> 5;
    const int g  = lane >> 2;
    const int t  = lane & 3;
    const int jj = lane >> 3;
    const int rr = lane & 7;
    const int wr = warp * 32;

    const int bh = blockIdx.y;
    const int b = bh >> 4;
    const int h = bh & 15;
    const int q0 = blockIdx.x * 256;

    const __half* qptr = g_q + (size_t)bh * SEQ * HDIM;
    const __half* kptr = g_k + (size_t)bh * SEQ * HDIM;
    const __half* vptr = g_v + (size_t)bh * SEQ * HDIM;

    const int row = tid >> 3;
    const int c8  = (tid & 7) * 8;

    // ---- Stage Q (256 x 64 fp16) ----
#pragma unroll
    for (int i = 0; i < 8; ++i) {
        int rw = row + i * 32;
        *(uint4*)&Qh[rw * HS + c8] = *(const uint4*)(qptr + (size_t)(q0 + rw) * HDIM + c8);
    }

    // ---- Issue K/V/mask tiles 0,1 ----
#pragma unroll
    for (int s = 0; s < 2; ++s) {
#pragma unroll
        for (int i = 0; i < 2; ++i) {
            int rw = row + i * 32;
            cp_async16(&smh[AK_H(s) + rw * HS + c8],
                       kptr + (size_t)(s * 64 + rw) * HDIM + c8);
            cp_async16(&smh[AV_H(s) + rw * HS + c8],
                       vptr + (size_t)(s * 64 + rw) * HDIM + c8);
        }
        if (tid < 16)
            cp_async16(&mskb[s * 64 + tid * 4], mask + (size_t)b * SEQ + s * 64 + tid * 4);
        CP_COMMIT();
    }
    __syncthreads();

    // ---- Q fragments (2 m-subtiles x 4 k-steps) ----
    uint32_t qa[2][4][4];
#pragma unroll
    for (int mt = 0; mt < 2; ++mt)
#pragma unroll
        for (int ks = 0; ks < 4; ++ks) {
            const __half* p = Qh + (wr + mt * 16 + (jj & 1) * 8 + rr) * HS
                            + ks * 16 + (jj >> 1) * 8;
            ldsm_x4((uint32_t)__cvta_generic_to_shared(p), qa[mt][ks]);
        }

    float oacc[2][8][4];
#pragma unroll
    for (int mt = 0; mt < 2; ++mt)
#pragma unroll
        for (int nt = 0; nt < 8; ++nt)
#pragma unroll
            for (int r = 0; r < 4; ++r) oacc[mt][nt][r] = 0.0f;
    float lacc[2][4] = {{0.0f, 0.0f, 0.0f, 0.0f}, {0.0f, 0.0f, 0.0f, 0.0f}};
    const uint32_t ONE2 = 0x3C003C00u;
    const uint32_t ones_b[2] = {ONE2, ONE2};

    int stage = 0;
    for (int j = 0; j < 32; ++j) {
        if (j < 31) { CP_WAIT(1); } else { CP_WAIT(0); }
        __syncthreads();

        if (j + 2 < 32) {
            int ns = stage + 2; if (ns >= 3) ns -= 3;
#pragma unroll
            for (int i = 0; i < 2; ++i) {
                int rw = row + i * 32;
                cp_async16(&smh[AK_H(ns) + rw * HS + c8],
                           kptr + (size_t)((j + 2) * 64 + rw) * HDIM + c8);
                cp_async16(&smh[AV_H(ns) + rw * HS + c8],
                           vptr + (size_t)((j + 2) * 64 + rw) * HDIM + c8);
            }
            if (tid < 16)
                cp_async16(&mskb[ns * 64 + tid * 4],
                           mask + (size_t)b * SEQ + (j + 2) * 64 + tid * 4);
            CP_COMMIT();
        }

        const __half* Kb = smh + AK_H(stage);
        const __half* Vb = smh + AV_H(stage);
        const float* mk = mskb + stage * 64;

        // ---- S = Q K^T ----
        float sacc[2][8][4];
#pragma unroll
        for (int mt = 0; mt < 2; ++mt)
#pragma unroll
            for (int nt = 0; nt < 8; ++nt)
#pragma unroll
                for (int r = 0; r < 4; ++r) sacc[mt][nt][r] = 0.0f;

#pragma unroll
        for (int ks = 0; ks < 4; ++ks) {
#pragma unroll
            for (int ntp = 0; ntp < 4; ++ntp) {
                uint32_t bb[4];
                const __half* p = Kb + (ntp * 16 + (jj >> 1) * 8 + rr) * HS
                                + ks * 16 + (jj & 1) * 8;
                ldsm_x4((uint32_t)__cvta_generic_to_shared(p), bb);
#pragma unroll
                for (int mt = 0; mt < 2; ++mt) {
                    mma16(sacc[mt][2 * ntp + 0], qa[mt][ks], &bb[0]);
                    mma16(sacc[mt][2 * ntp + 1], qa[mt][ks], &bb[2]);
                }
            }
        }

        // ---- softmax ----
        uint32_t ph[2][8][2];
#pragma unroll
        for (int mt = 0; mt < 2; ++mt) {
#pragma unroll
            for (int nt = 0; nt < 8; ++nt) {
                int col = nt * 8 + 2 * t;
                float m0f = mk[col] * LOG2E;
                float m1f = mk[col + 1] * LOG2E;
                const float cc = 0.125f * LOG2E;
                float y0 = fmaf(sacc[mt][nt][0], cc, m0f);
                float y1 = fmaf(sacc[mt][nt][1], cc, m1f);
                float y2 = fmaf(sacc[mt][nt][2], cc, m0f);
                float y3 = fmaf(sacc[mt][nt][3], cc, m1f);
                uint32_t a01 = h2u(__floats2half2_rn(y0, y1));
                uint32_t a23 = h2u(__floats2half2_rn(y2, y3));
                asm("ex2.approx.f16x2 %0, %1;" : "=r"(ph[mt][nt][0]) : "r"(a01));
                asm("ex2.approx.f16x2 %0, %1;" : "=r"(ph[mt][nt][1]) : "r"(a23));
            }
        }

        // ---- O += P V ; lsum += P 1 ----
#pragma unroll
        for (int ks = 0; ks < 4; ++ks) {
            uint32_t pa[2][4];
#pragma unroll
            for (int mt = 0; mt < 2; ++mt) {
                pa[mt][0] = ph[mt][2 * ks][0];
                pa[mt][1] = ph[mt][2 * ks][1];
                pa[mt][2] = ph[mt][2 * ks + 1][0];
                pa[mt][3] = ph[mt][2 * ks + 1][1];
                mma16(lacc[mt], pa[mt], ones_b);
            }
#pragma unroll
            for (int ntp = 0; ntp < 4; ++ntp) {
                uint32_t bb[4];
                const __half* p = Vb + (ks * 16 + (jj & 1) * 8 + rr) * HS
                                + ntp * 16 + (jj >> 1) * 8;
                ldsm_x4_t((uint32_t)__cvta_generic_to_shared(p), bb);
#pragma unroll
                for (int mt = 0; mt < 2; ++mt) {
                    mma16(oacc[mt][2 * ntp + 0], pa[mt], &bb[0]);
                    mma16(oacc[mt][2 * ntp + 1], pa[mt], &bb[2]);
                }
            }
        }

        ++stage; if (stage == 3) stage = 0;
    }

    // ---- Epilogue ----
#pragma unroll
    for (int mt = 0; mt < 2; ++mt) {
        float inv0 = 1.0f / lacc[mt][0];
        float inv1 = 1.0f / lacc[mt][2];
        float* orow0 = out + ((size_t)b * SEQ + q0 + wr + mt * 16 + g) * HID + h * HDIM;
        float* orow1 = orow0 + (size_t)8 * HID;
#pragma unroll
        for (int nt = 0; nt < 8; ++nt) {
            int col = nt * 8 + 2 * t;
            float2 v0 = { oacc[mt][nt][0] * inv0, oacc[mt][nt][1] * inv0 };
            float2 v1 = { oacc[mt][nt][2] * inv1, oacc[mt][nt][3] * inv1 };
            *(float2*)&orow0[col] = v0;
            *(float2*)&orow1[col] = v1;
        }
    }
}

extern "C" void kernel_launch(void* const* d_in, const int* in_sizes, int n_in,
                              void* d_out, int out_size)
{
    const float* hs   = (const float*)d_in[0];
    const float* mask = (const float*)d_in[1];
    const float* Wq   = (const float*)d_in[2];
    const float* bq   = (const float*)d_in[3];
    const float* Wk   = (const float*)d_in[4];
    const float* bk   = (const float*)d_in[5];
    const float* Wv   = (const float*)d_in[6];
    const float* bv   = (const float*)d_in[7];
    float* out = (float*)d_out;

    dim3 gc(2048, 4);
    convert_kernel<<<gc, 256>>>(hs, Wq, Wk, Wv);

    cudaFuncSetAttribute(qkv_kernel, cudaFuncAttributeMaxDynamicSharedMemorySize,
                         QKV_SMEM_BYTES);
    dim3 gq(HID / 128, (BATCH * SEQ) / 256, 3);   // (8, 16, 3) = 384 CTAs
    qkv_kernel<<<gq, 256, QKV_SMEM_BYTES>>>(bq, bk, bv);

    cudaFuncSetAttribute(attn_kernel, cudaFuncAttributeMaxDynamicSharedMemorySize,
                         ATTN_SMEM_BYTES);
    dim3 ga(SEQ / 256, BATCH * NHEADS);           // (8, 32) = 256 CTAs
    attn_kernel<<<ga, 256, ATTN_SMEM_BYTES>>>(mask, out);
}